// round 2
// baseline (speedup 1.0000x reference)
#include <cuda_runtime.h>
#include <cuda_bf16.h>
#include <cstdint>
#include <cstddef>

#define B_  32
#define T_  1024
#define D_  512
#define H_  512
#define G4H 2048
#define GRID_REC 128
#define TPB_REC  128

// ---------------- scratch (device globals: no allocation allowed) -------------
__device__ __align__(16) float  g_xz[(size_t)T_ * B_ * G4H]; // [t][b][4H] pre-activations
__device__ __align__(16) float2 g_h[2][16 * H_];             // [buf][pair(16)][d(512)]
__device__ unsigned g_bar;                                    // grid barrier (monotonic)
__device__ unsigned g_exit;                                   // exit tickets (for reset)

// ---------------- helpers ----------------------------------------------------
union F2U { float2 f; unsigned long long u; };

__device__ __forceinline__ void ffma2(float2& d, float2 a, float2 b) {
    F2U D, A, Bv; D.f = d; A.f = a; Bv.f = b;
    asm("fma.rn.f32x2 %0, %1, %2, %0;" : "+l"(D.u) : "l"(A.u), "l"(Bv.u));
    d = D.f;
}

__device__ __forceinline__ float sigf(float x) {
    return __fdividef(1.f, 1.f + __expf(-x));
}
__device__ __forceinline__ float tanf_(float x) {
    return 2.f * sigf(2.f * x) - 1.f;
}
__device__ __forceinline__ float2 sig2(float2 v) { return make_float2(sigf(v.x), sigf(v.y)); }
__device__ __forceinline__ float2 th2(float2 v)  { return make_float2(tanf_(v.x), tanf_(v.y)); }
__device__ __forceinline__ float2 f2add(float2 a, float2 b) { return make_float2(a.x + b.x, a.y + b.y); }

// lengths dtype robustness: JAX default (x64 off) makes "int64" silently int32.
// Detect using ONLY the first 128 bytes (safe under either dtype): if all 16
// odd int32 slots are zero, the data is real little-endian int64.
__device__ __forceinline__ int read_length(const int* L32, int b) {
    bool is64 = true;
    #pragma unroll
    for (int i = 1; i < 32; i += 2) is64 &= (L32[i] == 0);
    return is64 ? L32[2 * b] : L32[b];
}

// ---------------- kernel 1: xz = X @ Wx + bias --------------------------------
// M = 32768 rows (m = t*32 + b), N = 2048, K = 512. CTA tile 128x128, thread 8x8.
__global__ void __launch_bounds__(256) gemm_xw_kernel(
    const float* __restrict__ X,
    const float* __restrict__ Wx,
    const float* __restrict__ bias)
{
    __shared__ __align__(16) float2 ash[16][128];  // A duplicated (a,a)  [kk][row]
    __shared__ __align__(16) float2 bsh[16][64];   // B as col-pairs      [kk][npair]

    const int tid = threadIdx.x;
    const int n0 = blockIdx.x * 128;
    const int m0 = blockIdx.y * 128;
    const int rg = tid >> 4, cg = tid & 15;
    const int r0 = rg * 8, np0 = cg * 4;

    float2 acc[8][4];
    #pragma unroll
    for (int r = 0; r < 8; r++)
        #pragma unroll
        for (int c = 0; c < 4; c++) acc[r][c] = make_float2(0.f, 0.f);

    for (int k0 = 0; k0 < D_; k0 += 16) {
        // stage A tile: 128 rows x 16 k  (m -> (t,b); X is [b][t][d])
        #pragma unroll
        for (int i = 0; i < 2; i++) {
            int q = tid + i * 256;               // 0..511 float4 slots
            int row = q >> 2, kk4 = (q & 3) * 4;
            int m = m0 + row, t = m >> 5, b = m & 31;
            float4 v = *(const float4*)(X + ((size_t)b * T_ + t) * D_ + k0 + kk4);
            ash[kk4 + 0][row] = make_float2(v.x, v.x);
            ash[kk4 + 1][row] = make_float2(v.y, v.y);
            ash[kk4 + 2][row] = make_float2(v.z, v.z);
            ash[kk4 + 3][row] = make_float2(v.w, v.w);
        }
        // stage B tile: 16 k x 128 n
        #pragma unroll
        for (int i = 0; i < 2; i++) {
            int q = tid + i * 256;
            int kk = q >> 5, nn4 = (q & 31) * 4;
            float4 v = *(const float4*)(Wx + (size_t)(k0 + kk) * G4H + n0 + nn4);
            bsh[kk][(nn4 >> 1) + 0] = make_float2(v.x, v.y);
            bsh[kk][(nn4 >> 1) + 1] = make_float2(v.z, v.w);
        }
        __syncthreads();

        #pragma unroll
        for (int kk = 0; kk < 16; kk++) {
            float2 a[8], bb[4];
            #pragma unroll
            for (int i = 0; i < 4; i++) {
                float4 v = *(const float4*)&ash[kk][r0 + i * 2];
                a[i * 2 + 0] = make_float2(v.x, v.y);
                a[i * 2 + 1] = make_float2(v.z, v.w);
            }
            #pragma unroll
            for (int i = 0; i < 2; i++) {
                float4 v = *(const float4*)&bsh[kk][np0 + i * 2];
                bb[i * 2 + 0] = make_float2(v.x, v.y);
                bb[i * 2 + 1] = make_float2(v.z, v.w);
            }
            #pragma unroll
            for (int r = 0; r < 8; r++)
                #pragma unroll
                for (int c = 0; c < 4; c++)
                    ffma2(acc[r][c], a[r], bb[c]);
        }
        __syncthreads();
    }

    #pragma unroll
    for (int r = 0; r < 8; r++) {
        int m = m0 + r0 + r;
        #pragma unroll
        for (int c = 0; c < 4; c++) {
            int n = n0 + (np0 + c) * 2;
            float2 bv = *(const float2*)(bias + n);
            float2 o = make_float2(acc[r][c].x + bv.x, acc[r][c].y + bv.y);
            *(float2*)(g_xz + (size_t)m * G4H + n) = o;
        }
    }
}

// ---------------- kernel 2: persistent recurrence -----------------------------
// 128 CTAs x 128 threads. CTA g owns hidden units [4g, 4g+4) -> 16 gate columns.
// Wh slice lives in SMEM for the whole kernel. h exchanged via global double
// buffer (L2 only, __ldcg). Grid barrier: monotonic atomic counter.
__global__ void __launch_bounds__(TPB_REC) lstm_rec_kernel(
    const float* __restrict__ Wh,
    const int* __restrict__ lengths_raw,
    float* __restrict__ out)
{
    extern __shared__ __align__(16) char smem[];
    float2* wsh = (float2*)smem;                    // [16 cols][512 d] duplicated (w,w)
    float2* hsh = (float2*)(smem + 65536);          // [16 pairs][512 d]
    float2* zsh = (float2*)(smem + 131072);         // [2 khalf][16 cols][16 pairs]
    float2* csh = (float2*)(smem + 131072 + 4096);  // [4 units][16 pairs]

    const int tid = threadIdx.x;
    const int u0 = blockIdx.x * 4;

    // Preload Wh columns (once for all 1024 steps)
    for (int idx = tid; idx < 16 * 512; idx += TPB_REC) {
        int c = idx >> 9, d = idx & 511;
        int gcol = (c >> 2) * H_ + u0 + (c & 3);    // local col -> global gate col
        float w = Wh[(size_t)d * G4H + gcol];
        wsh[idx] = make_float2(w, w);
    }
    if (tid < 64) csh[tid] = make_float2(0.f, 0.f);
    __syncthreads();

    // inner-loop decomposition: thread = (khalf, colpair cg, pairpair pg)
    const int kh = tid & 1;
    const int id2 = tid >> 1;
    const int cg = id2 & 7;       // 2 cols each
    const int pg = id2 >> 3;      // 2 batch-pairs each
    const int dbase = kh * 256;
    const float4* wp0 = (const float4*)(wsh + (cg * 2 + 0) * 512 + dbase);
    const float4* wp1 = (const float4*)(wsh + (cg * 2 + 1) * 512 + dbase);
    const float4* hp0 = (const float4*)(hsh + (pg * 2 + 0) * 512 + dbase);
    const float4* hp1 = (const float4*)(hsh + (pg * 2 + 1) * 512 + dbase);

    const int gu = tid >> 4;      // gate-phase unit   (tid < 64)
    const int gp = tid & 15;      // gate-phase pair

    for (int t = 0; t < T_; t++) {
        const int rb = t & 1, wb = rb ^ 1;

        // prefetch xz for this step (gate threads), overlaps with inner loop
        float xza[4], xzb[4];
        if (tid < 64) {
            size_t base = ((size_t)t * B_ + gp * 2) * G4H + u0 + gu;
            #pragma unroll
            for (int g = 0; g < 4; g++) {
                xza[g] = __ldg((const float*)g_xz + base + (size_t)g * H_);
                xzb[g] = __ldg((const float*)g_xz + base + G4H + (size_t)g * H_);
            }
        }

        float2 aE0, aE1, aE2, aE3, aO0, aO1, aO2, aO3;
        aE0 = aE1 = aE2 = aE3 = aO0 = aO1 = aO2 = aO3 = make_float2(0.f, 0.f);

        if (t > 0) {
            // stage fresh h: 64KB from L2 (must bypass L1 — other SMs wrote it)
            const float4* src = (const float4*)(g_h[rb]);
            float4* dst = (float4*)hsh;
            #pragma unroll
            for (int i = 0; i < 32; i++)
                dst[tid + i * TPB_REC] = __ldcg(src + tid + i * TPB_REC);
            __syncthreads();

            #pragma unroll 8
            for (int dd = 0; dd < 128; dd++) {   // 2 d's per iter over this k-half
                float4 h0 = hp0[dd], h1 = hp1[dd];
                float4 w0 = wp0[dd], w1 = wp1[dd];
                ffma2(aE0, make_float2(h0.x, h0.y), make_float2(w0.x, w0.y));
                ffma2(aO0, make_float2(h0.z, h0.w), make_float2(w0.z, w0.w));
                ffma2(aE1, make_float2(h1.x, h1.y), make_float2(w0.x, w0.y));
                ffma2(aO1, make_float2(h1.z, h1.w), make_float2(w0.z, w0.w));
                ffma2(aE2, make_float2(h0.x, h0.y), make_float2(w1.x, w1.y));
                ffma2(aO2, make_float2(h0.z, h0.w), make_float2(w1.z, w1.w));
                ffma2(aE3, make_float2(h1.x, h1.y), make_float2(w1.x, w1.y));
                ffma2(aO3, make_float2(h1.z, h1.w), make_float2(w1.z, w1.w));
            }
        }

        // write k-half partials
        {
            float2* zb = zsh + kh * 256;
            int c0 = cg * 2, p0 = pg * 2;
            zb[(c0 + 0) * 16 + p0 + 0] = f2add(aE0, aO0);
            zb[(c0 + 0) * 16 + p0 + 1] = f2add(aE1, aO1);
            zb[(c0 + 1) * 16 + p0 + 0] = f2add(aE2, aO2);
            zb[(c0 + 1) * 16 + p0 + 1] = f2add(aE3, aO3);
        }
        __syncthreads();

        // gates: 64 threads = 4 units x 16 batch-pairs
        if (tid < 64) {
            float2 z[4];
            #pragma unroll
            for (int g = 0; g < 4; g++) {
                int c = g * 4 + gu;
                float2 za = zsh[c * 16 + gp];
                float2 zc = zsh[256 + c * 16 + gp];
                z[g] = make_float2(za.x + zc.x + xza[g], za.y + zc.y + xzb[g]);
            }
            float2 ig = sig2(z[0]);
            float2 fg = sig2(z[1]);
            float2 gg = th2(z[2]);
            float2 og = sig2(z[3]);
            float2 cold = csh[gu * 16 + gp];
            float2 nc = make_float2(fg.x * cold.x + ig.x * gg.x,
                                    fg.y * cold.y + ig.y * gg.y);
            float2 tc = th2(nc);
            float2 nh = make_float2(og.x * tc.x, og.y * tc.y);
            csh[gu * 16 + gp] = nc;

            int uu = u0 + gu;
            g_h[wb][gp * 512 + uu] = nh;
            out[((size_t)(2 * gp + 0) * T_ + t) * H_ + uu] = nh.x;
            out[((size_t)(2 * gp + 1) * T_ + t) * H_ + uu] = nh.y;
            __threadfence();
        }
        __syncthreads();

        // grid barrier (monotonic counter; all 128 CTAs co-resident)
        if (tid == 0) {
            atomicAdd(&g_bar, 1u);
            unsigned target = (unsigned)(t + 1) * GRID_REC;
            while (*((volatile unsigned*)&g_bar) < target) { }
        }
        __syncthreads();
    }

    // final states: CTA owns units u0..u0+3 and wrote all their outputs
    for (int idx = tid; idx < 128; idx += TPB_REC) {
        int b = idx >> 2, uu = u0 + (idx & 3);
        int len = read_length(lengths_raw, b);
        int lt = len > 0 ? len - 1 : 0;
        if (lt > T_ - 1) lt = T_ - 1;
        out[(size_t)B_ * T_ * H_ + (size_t)b * H_ + uu] =
            out[((size_t)b * T_ + (size_t)lt) * H_ + uu];
    }
    __syncthreads();

    // reset barrier counters so the next graph replay starts clean.
    // last exiter (ticket == GRID-1) knows every CTA passed every spin.
    if (tid == 0) {
        unsigned ticket = atomicAdd(&g_exit, 1u);
        if (ticket == GRID_REC - 1) {
            g_bar = 0;
            g_exit = 0;
            __threadfence();
        }
    }
}

// ---------------- launch ------------------------------------------------------
extern "C" void kernel_launch(void* const* d_in, const int* in_sizes, int n_in,
                              void* d_out, int out_size)
{
    const float* X       = (const float*)d_in[0];
    const int*   lengths = (const int*)d_in[1];   // int32 (JAX x64-off) or int64; autodetected
    const float* Wx      = (const float*)d_in[2];
    const float* Wh      = (const float*)d_in[3];
    const float* bias    = (const float*)d_in[4];
    float*       out     = (float*)d_out;

    dim3 g1(G4H / 128, (B_ * T_) / 128);
    gemm_xw_kernel<<<g1, 256>>>(X, Wx, bias);

    static const size_t SMEM_REC = 65536 + 65536 + 4096 + 512;  // 135,680 B
    cudaFuncSetAttribute(lstm_rec_kernel,
                         cudaFuncAttributeMaxDynamicSharedMemorySize, (int)SMEM_REC);
    lstm_rec_kernel<<<GRID_REC, TPB_REC, SMEM_REC>>>(Wh, lengths, out);
}

// round 3
// speedup vs baseline: 2.4881x; 2.4881x over previous
#include <cuda_runtime.h>
#include <cuda_bf16.h>
#include <cstdint>
#include <cstddef>

#define B_  32
#define T_  1024
#define D_  512
#define H_  512
#define G4H 2048
#define GRID_REC 128
#define TPB_REC  128

// ---------------- scratch (device globals: no allocation allowed) -------------
__device__ __align__(16) float  g_xz[(size_t)T_ * B_ * G4H]; // [t][b][4H] pre-activations
__device__ __align__(16) float2 g_h[2][H_ * 16];             // [buf][d(512)][pair(16)]
__device__ unsigned g_bar;                                    // grid barrier (monotonic)
__device__ unsigned g_exit;                                   // exit tickets (for reset)

// ---------------- helpers ----------------------------------------------------
union F2U { float2 f; unsigned long long u; };

__device__ __forceinline__ void ffma2(float2& d, float2 a, float2 b) {
    F2U D, A, Bv; D.f = d; A.f = a; Bv.f = b;
    asm("fma.rn.f32x2 %0, %1, %2, %0;" : "+l"(D.u) : "l"(A.u), "l"(Bv.u));
    d = D.f;
}

__device__ __forceinline__ float sigf(float x) {
    return __fdividef(1.f, 1.f + __expf(-x));
}
__device__ __forceinline__ float tanf_(float x) {
    return 2.f * sigf(2.f * x) - 1.f;
}
__device__ __forceinline__ float2 sig2(float2 v) { return make_float2(sigf(v.x), sigf(v.y)); }
__device__ __forceinline__ float2 th2(float2 v)  { return make_float2(tanf_(v.x), tanf_(v.y)); }

// lengths dtype robustness: JAX default (x64 off) makes "int64" silently int32.
// Detect using ONLY the first 128 bytes (safe under either dtype): if all 16
// odd int32 slots are zero, the data is real little-endian int64.
__device__ __forceinline__ int read_length(const int* L32, int b) {
    bool is64 = true;
    #pragma unroll
    for (int i = 1; i < 32; i += 2) is64 &= (L32[i] == 0);
    return is64 ? L32[2 * b] : L32[b];
}

// ---------------- kernel 1: xz = X @ Wx + bias --------------------------------
// M = 32768 rows (m = t*32 + b), N = 2048, K = 512. CTA tile 128x128, thread 8x8.
__global__ void __launch_bounds__(256) gemm_xw_kernel(
    const float* __restrict__ X,
    const float* __restrict__ Wx,
    const float* __restrict__ bias)
{
    __shared__ __align__(16) float2 ash[16][128];  // A duplicated (a,a)  [kk][row]
    __shared__ __align__(16) float2 bsh[16][64];   // B as col-pairs      [kk][npair]

    const int tid = threadIdx.x;
    const int n0 = blockIdx.x * 128;
    const int m0 = blockIdx.y * 128;
    const int rg = tid >> 4, cg = tid & 15;
    const int r0 = rg * 8, np0 = cg * 4;

    float2 acc[8][4];
    #pragma unroll
    for (int r = 0; r < 8; r++)
        #pragma unroll
        for (int c = 0; c < 4; c++) acc[r][c] = make_float2(0.f, 0.f);

    for (int k0 = 0; k0 < D_; k0 += 16) {
        #pragma unroll
        for (int i = 0; i < 2; i++) {
            int q = tid + i * 256;               // 0..511 float4 slots
            int row = q >> 2, kk4 = (q & 3) * 4;
            int m = m0 + row, t = m >> 5, b = m & 31;
            float4 v = *(const float4*)(X + ((size_t)b * T_ + t) * D_ + k0 + kk4);
            ash[kk4 + 0][row] = make_float2(v.x, v.x);
            ash[kk4 + 1][row] = make_float2(v.y, v.y);
            ash[kk4 + 2][row] = make_float2(v.z, v.z);
            ash[kk4 + 3][row] = make_float2(v.w, v.w);
        }
        #pragma unroll
        for (int i = 0; i < 2; i++) {
            int q = tid + i * 256;
            int kk = q >> 5, nn4 = (q & 31) * 4;
            float4 v = *(const float4*)(Wx + (size_t)(k0 + kk) * G4H + n0 + nn4);
            bsh[kk][(nn4 >> 1) + 0] = make_float2(v.x, v.y);
            bsh[kk][(nn4 >> 1) + 1] = make_float2(v.z, v.w);
        }
        __syncthreads();

        #pragma unroll
        for (int kk = 0; kk < 16; kk++) {
            float2 a[8], bb[4];
            #pragma unroll
            for (int i = 0; i < 4; i++) {
                float4 v = *(const float4*)&ash[kk][r0 + i * 2];
                a[i * 2 + 0] = make_float2(v.x, v.y);
                a[i * 2 + 1] = make_float2(v.z, v.w);
            }
            #pragma unroll
            for (int i = 0; i < 2; i++) {
                float4 v = *(const float4*)&bsh[kk][np0 + i * 2];
                bb[i * 2 + 0] = make_float2(v.x, v.y);
                bb[i * 2 + 1] = make_float2(v.z, v.w);
            }
            #pragma unroll
            for (int r = 0; r < 8; r++)
                #pragma unroll
                for (int c = 0; c < 4; c++)
                    ffma2(acc[r][c], a[r], bb[c]);
        }
        __syncthreads();
    }

    #pragma unroll
    for (int r = 0; r < 8; r++) {
        int m = m0 + r0 + r;
        #pragma unroll
        for (int c = 0; c < 4; c++) {
            int n = n0 + (np0 + c) * 2;
            float2 bv = *(const float2*)(bias + n);
            float2 o = make_float2(acc[r][c].x + bv.x, acc[r][c].y + bv.y);
            *(float2*)(g_xz + (size_t)m * G4H + n) = o;
        }
    }
}

// ---------------- kernel 2: persistent recurrence -----------------------------
// 128 CTAs x 128 threads. CTA g owns hidden units [4g, 4g+4) -> 16 gate columns
// (local col c = gate*4 + unit). d-MAJOR smem layouts (conflict-free):
//   wsh[d][16 cols]  (w,w) float2, d-stride 128B
//   hsh[d][16 pairs] float2,       d-stride 128B
// Thread (cq,pq,ks): cols cq*4..+3, pairs pq*4..+3, d in [ks*64, ks*64+64).
__global__ void __launch_bounds__(TPB_REC) lstm_rec_kernel(
    const float* __restrict__ Wh,
    const int* __restrict__ lengths_raw,
    float* __restrict__ out)
{
    extern __shared__ __align__(16) char smem[];
    float2* wsh = (float2*)smem;                      // [512 d][16 cols] (w,w)
    float2* hsh = (float2*)(smem + 65536);            // [512 d][16 pairs]
    float2* zsh = (float2*)(smem + 131072);           // [8 ks][16 cols][16 pairs]
    float2* csh = (float2*)(smem + 131072 + 16384);   // [4 units][16 pairs]

    const int tid = threadIdx.x;
    const int u0 = blockIdx.x * 4;

    // Preload Wh (once). wsh[d*16 + c] = (w,w), c = gate*4 + unit_local.
    for (int idx = tid; idx < 512 * 16; idx += TPB_REC) {
        int d = idx >> 4, c = idx & 15;
        int gcol = (c >> 2) * H_ + u0 + (c & 3);
        float w = Wh[(size_t)d * G4H + gcol];
        wsh[idx] = make_float2(w, w);
    }
    if (tid < 64) csh[tid] = make_float2(0.f, 0.f);
    __syncthreads();

    const int cq = tid & 3;
    const int pq = (tid >> 2) & 3;
    const int ks = tid >> 4;          // 0..7, 64 d each
    const int dbase = ks * 64;

    const float4* wf = ((const float4*)wsh) + (size_t)dbase * 8 + cq * 2;
    const float4* hf = ((const float4*)hsh) + (size_t)dbase * 8 + pq * 2;

    const int gu = tid >> 4;          // gate-phase unit (tid < 64)
    const int gp = tid & 15;          // gate-phase pair

    for (int t = 0; t < T_; t++) {
        const int rb = t & 1, wb = rb ^ 1;

        // prefetch xz (gate threads) — DRAM latency hidden behind main loop
        float xza[4], xzb[4];
        if (tid < 64) {
            size_t base = ((size_t)t * B_ + gp * 2) * G4H + u0 + gu;
            #pragma unroll
            for (int g = 0; g < 4; g++) {
                xza[g] = __ldg((const float*)g_xz + base + (size_t)g * H_);
                xzb[g] = __ldg((const float*)g_xz + base + G4H + (size_t)g * H_);
            }
        }

        float2 acc[4][4];
        #pragma unroll
        for (int j = 0; j < 4; j++)
            #pragma unroll
            for (int p = 0; p < 4; p++) acc[j][p] = make_float2(0.f, 0.f);

        if (t > 0) {
            // stage fresh h: 64KB from L2 (bypass L1 — other SMs wrote it)
            const float4* src = (const float4*)(g_h[rb]);
            float4* dst = (float4*)hsh;
            #pragma unroll
            for (int i = 0; i < 32; i++)
                dst[tid + i * TPB_REC] = __ldcg(src + tid + i * TPB_REC);
            __syncthreads();

            #pragma unroll 4
            for (int d = 0; d < 64; d++) {
                float4 wA = wf[d * 8], wB = wf[d * 8 + 1];
                float4 hA = hf[d * 8], hB = hf[d * 8 + 1];
                float2 w0 = make_float2(wA.x, wA.y), w1 = make_float2(wA.z, wA.w);
                float2 w2 = make_float2(wB.x, wB.y), w3 = make_float2(wB.z, wB.w);
                float2 h0 = make_float2(hA.x, hA.y), h1 = make_float2(hA.z, hA.w);
                float2 h2 = make_float2(hB.x, hB.y), h3 = make_float2(hB.z, hB.w);
                ffma2(acc[0][0], h0, w0); ffma2(acc[0][1], h1, w0);
                ffma2(acc[0][2], h2, w0); ffma2(acc[0][3], h3, w0);
                ffma2(acc[1][0], h0, w1); ffma2(acc[1][1], h1, w1);
                ffma2(acc[1][2], h2, w1); ffma2(acc[1][3], h3, w1);
                ffma2(acc[2][0], h0, w2); ffma2(acc[2][1], h1, w2);
                ffma2(acc[2][2], h2, w2); ffma2(acc[2][3], h3, w2);
                ffma2(acc[3][0], h0, w3); ffma2(acc[3][1], h1, w3);
                ffma2(acc[3][2], h2, w3); ffma2(acc[3][3], h3, w3);
            }
        }

        // write partials: zsh[ks][col cq*4+j][pair pq*4 .. +3] as 2x float4
        #pragma unroll
        for (int j = 0; j < 4; j++) {
            float2* zp = zsh + (size_t)ks * 256 + (cq * 4 + j) * 16 + pq * 4;
            *(float4*)(zp + 0) = make_float4(acc[j][0].x, acc[j][0].y,
                                             acc[j][1].x, acc[j][1].y);
            *(float4*)(zp + 2) = make_float4(acc[j][2].x, acc[j][2].y,
                                             acc[j][3].x, acc[j][3].y);
        }
        __syncthreads();

        // gates: 64 threads = 4 units x 16 batch-pairs
        if (tid < 64) {
            float2 z[4];
            #pragma unroll
            for (int g = 0; g < 4; g++) {
                int c = g * 4 + gu;
                float2 s = make_float2(xza[g], xzb[g]);
                #pragma unroll
                for (int k = 0; k < 8; k++) {
                    float2 v = zsh[k * 256 + c * 16 + gp];
                    s.x += v.x; s.y += v.y;
                }
                z[g] = s;
            }
            float2 ig = sig2(z[0]);
            float2 fg = sig2(z[1]);
            float2 gg = th2(z[2]);
            float2 og = sig2(z[3]);
            float2 cold = csh[gu * 16 + gp];
            float2 nc = make_float2(fg.x * cold.x + ig.x * gg.x,
                                    fg.y * cold.y + ig.y * gg.y);
            float2 tc = th2(nc);
            float2 nh = make_float2(og.x * tc.x, og.y * tc.y);
            csh[gu * 16 + gp] = nc;

            int uu = u0 + gu;
            g_h[wb][uu * 16 + gp] = nh;               // [d][pair] layout
            out[((size_t)(2 * gp + 0) * T_ + t) * H_ + uu] = nh.x;
            out[((size_t)(2 * gp + 1) * T_ + t) * H_ + uu] = nh.y;
            __threadfence();
        }
        __syncthreads();

        // grid barrier (monotonic counter; all 128 CTAs co-resident)
        if (tid == 0) {
            atomicAdd(&g_bar, 1u);
            unsigned target = (unsigned)(t + 1) * GRID_REC;
            while (*((volatile unsigned*)&g_bar) < target) { }
        }
        __syncthreads();
    }

    // final states
    for (int idx = tid; idx < 128; idx += TPB_REC) {
        int b = idx >> 2, uu = u0 + (idx & 3);
        int len = read_length(lengths_raw, b);
        int lt = len > 0 ? len - 1 : 0;
        if (lt > T_ - 1) lt = T_ - 1;
        out[(size_t)B_ * T_ * H_ + (size_t)b * H_ + uu] =
            out[((size_t)b * T_ + (size_t)lt) * H_ + uu];
    }
    __syncthreads();

    // reset barrier counters so the next graph replay starts clean
    if (tid == 0) {
        unsigned ticket = atomicAdd(&g_exit, 1u);
        if (ticket == GRID_REC - 1) {
            g_bar = 0;
            g_exit = 0;
            __threadfence();
        }
    }
}

// ---------------- launch ------------------------------------------------------
extern "C" void kernel_launch(void* const* d_in, const int* in_sizes, int n_in,
                              void* d_out, int out_size)
{
    const float* X       = (const float*)d_in[0];
    const int*   lengths = (const int*)d_in[1];   // int32/int64 autodetected
    const float* Wx      = (const float*)d_in[2];
    const float* Wh      = (const float*)d_in[3];
    const float* bias    = (const float*)d_in[4];
    float*       out     = (float*)d_out;

    dim3 g1(G4H / 128, (B_ * T_) / 128);
    gemm_xw_kernel<<<g1, 256>>>(X, Wx, bias);

    static const size_t SMEM_REC = 65536 + 65536 + 16384 + 512;  // 148,992 B
    cudaFuncSetAttribute(lstm_rec_kernel,
                         cudaFuncAttributeMaxDynamicSharedMemorySize, (int)SMEM_REC);
    lstm_rec_kernel<<<GRID_REC, TPB_REC, SMEM_REC>>>(Wh, lengths, out);
}

// round 4
// speedup vs baseline: 3.1834x; 1.2794x over previous
#include <cuda_runtime.h>
#include <cuda_bf16.h>
#include <cstdint>
#include <cstddef>

#define B_  32
#define T_  1024
#define D_  512
#define H_  512
#define G4H 2048
#define GB  4        // batch groups (8 batches each)
#define GU  32       // unit groups (16 units each)
#define GRID_REC (GB * GU)
#define TPB_REC  256

// ---------------- scratch (device globals: no allocation allowed) -------------
__device__ __align__(16) float g_xz[(size_t)T_ * B_ * G4H]; // [t][b][4H]
__device__ __align__(16) float g_hf[2][GB][512 * 8];        // [buf][grp][unit(512)][b(8)]
__device__ unsigned g_bar4[GB * 32];                         // 1 counter / 128B line
__device__ unsigned g_exit4[GB * 32];

// ---------------- helpers ----------------------------------------------------
union F2U { float2 f; unsigned long long u; };

__device__ __forceinline__ void ffma2(float2& d, float2 a, float2 b) {
    F2U D, A, Bv; D.f = d; A.f = a; Bv.f = b;
    asm("fma.rn.f32x2 %0, %1, %2, %0;" : "+l"(D.u) : "l"(A.u), "l"(Bv.u));
    d = D.f;
}
__device__ __forceinline__ float sigf(float x) {
    return __fdividef(1.f, 1.f + __expf(-x));
}
__device__ __forceinline__ float tanf_(float x) {
    return 2.f * sigf(2.f * x) - 1.f;
}
__device__ __forceinline__ float2 sig2(float2 v) { return make_float2(sigf(v.x), sigf(v.y)); }
__device__ __forceinline__ float2 th2(float2 v)  { return make_float2(tanf_(v.x), tanf_(v.y)); }

// lengths dtype robustness: JAX x64-off makes "int64" silently int32. Detect
// using only the first 128 bytes: all 16 odd int32 slots zero => real int64.
__device__ __forceinline__ int read_length(const int* L32, int b) {
    bool is64 = true;
    #pragma unroll
    for (int i = 1; i < 32; i += 2) is64 &= (L32[i] == 0);
    return is64 ? L32[2 * b] : L32[b];
}

// ---------------- kernel 1: xz = X @ Wx + bias --------------------------------
// M=32768 (m = t*32+b), N=2048, K=512. 128x128 tile, 8x8/thread, reg prefetch.
__global__ void __launch_bounds__(256, 2) gemm_xw_kernel(
    const float* __restrict__ X,
    const float* __restrict__ Wx,
    const float* __restrict__ bias)
{
    __shared__ __align__(16) float2 ash[16][128];  // A dup (a,a)  [kk][row]
    __shared__ __align__(16) float2 bsh[16][64];   // B col-pairs  [kk][npair]

    const int tid = threadIdx.x;
    const int n0 = blockIdx.x * 128;
    const int m0 = blockIdx.y * 128;
    const int rg = tid >> 4, cg = tid & 15;
    const int r0 = rg * 8, np0 = cg * 4;

    // per-thread staging coords
    int qa0 = tid, qa1 = tid + 256;
    int rowA0 = qa0 >> 2, kkA0 = (qa0 & 3) * 4;
    int rowA1 = qa1 >> 2, kkA1 = (qa1 & 3) * 4;
    int mA0 = m0 + rowA0, tA0 = mA0 >> 5, bA0 = mA0 & 31;
    int mA1 = m0 + rowA1, tA1 = mA1 >> 5, bA1 = mA1 & 31;
    const float* pA0 = X + ((size_t)bA0 * T_ + tA0) * D_ + kkA0;
    const float* pA1 = X + ((size_t)bA1 * T_ + tA1) * D_ + kkA1;
    int kkB0 = qa0 >> 5, nnB0 = (qa0 & 31) * 4;
    int kkB1 = qa1 >> 5, nnB1 = (qa1 & 31) * 4;
    const float* pB0 = Wx + (size_t)kkB0 * G4H + n0 + nnB0;
    const float* pB1 = Wx + (size_t)kkB1 * G4H + n0 + nnB1;

    float2 acc[8][4];
    #pragma unroll
    for (int r = 0; r < 8; r++)
        #pragma unroll
        for (int c = 0; c < 4; c++) acc[r][c] = make_float2(0.f, 0.f);

    float4 ra0 = *(const float4*)pA0;
    float4 ra1 = *(const float4*)pA1;
    float4 rb0 = *(const float4*)pB0;
    float4 rb1 = *(const float4*)pB1;

    for (int k0 = 0; k0 < D_; k0 += 16) {
        ash[kkA0 + 0][rowA0] = make_float2(ra0.x, ra0.x);
        ash[kkA0 + 1][rowA0] = make_float2(ra0.y, ra0.y);
        ash[kkA0 + 2][rowA0] = make_float2(ra0.z, ra0.z);
        ash[kkA0 + 3][rowA0] = make_float2(ra0.w, ra0.w);
        ash[kkA1 + 0][rowA1] = make_float2(ra1.x, ra1.x);
        ash[kkA1 + 1][rowA1] = make_float2(ra1.y, ra1.y);
        ash[kkA1 + 2][rowA1] = make_float2(ra1.z, ra1.z);
        ash[kkA1 + 3][rowA1] = make_float2(ra1.w, ra1.w);
        bsh[kkB0][(nnB0 >> 1) + 0] = make_float2(rb0.x, rb0.y);
        bsh[kkB0][(nnB0 >> 1) + 1] = make_float2(rb0.z, rb0.w);
        bsh[kkB1][(nnB1 >> 1) + 0] = make_float2(rb1.x, rb1.y);
        bsh[kkB1][(nnB1 >> 1) + 1] = make_float2(rb1.z, rb1.w);
        __syncthreads();

        if (k0 + 16 < D_) {       // prefetch next tile into regs (overlaps compute)
            ra0 = *(const float4*)(pA0 + k0 + 16);
            ra1 = *(const float4*)(pA1 + k0 + 16);
            rb0 = *(const float4*)(pB0 + (size_t)(k0 + 16) * G4H);
            rb1 = *(const float4*)(pB1 + (size_t)(k0 + 16) * G4H);
        }

        #pragma unroll
        for (int kk = 0; kk < 16; kk++) {
            float2 a[8], bb[4];
            #pragma unroll
            for (int i = 0; i < 4; i++) {
                float4 v = *(const float4*)&ash[kk][r0 + i * 2];
                a[i * 2 + 0] = make_float2(v.x, v.y);
                a[i * 2 + 1] = make_float2(v.z, v.w);
            }
            #pragma unroll
            for (int i = 0; i < 2; i++) {
                float4 v = *(const float4*)&bsh[kk][np0 + i * 2];
                bb[i * 2 + 0] = make_float2(v.x, v.y);
                bb[i * 2 + 1] = make_float2(v.z, v.w);
            }
            #pragma unroll
            for (int r = 0; r < 8; r++)
                #pragma unroll
                for (int c = 0; c < 4; c++)
                    ffma2(acc[r][c], a[r], bb[c]);
        }
        __syncthreads();
    }

    #pragma unroll
    for (int r = 0; r < 8; r++) {
        int m = m0 + r0 + r;
        #pragma unroll
        for (int c = 0; c < 4; c++) {
            int n = n0 + (np0 + c) * 2;
            float2 bv = *(const float2*)(bias + n);
            float2 o = make_float2(acc[r][c].x + bv.x, acc[r][c].y + bv.y);
            *(float2*)(g_xz + (size_t)m * G4H + n) = o;
        }
    }
}

// ---------------- kernel 2: persistent recurrence -----------------------------
// Grid 128 = 4 batch-groups x 32 unit-groups. CTA (gb,gu): batches 8gb..+7,
// units 16gu..+15 (64 gate cols = 32 col-PAIRS). SMEM:
//   wsh[512 d][32 cp] float2 = (w_even, w_odd)           128KB
//   hsh[512 d][8 b]   float2 = (h_b, h_b) duplicated      32KB
//   zsh[16 ks][32 cp][8 b] float2 partials                32KB
//   csh[8 up][8 b]    float2 c-state (2 units)            512B
// Thread (cpq 0..7, bq 0..1, ks 0..15): 4 cp x 4 b x 32 d.
__global__ void __launch_bounds__(TPB_REC) lstm_rec_kernel(
    const float* __restrict__ Wh,
    const int* __restrict__ lengths_raw,
    float* __restrict__ out)
{
    extern __shared__ __align__(16) char smem[];
    float2* wsh = (float2*)smem;                       // 512*32
    float2* hsh = (float2*)(smem + 131072);            // 512*8
    float2* zsh = (float2*)(smem + 131072 + 32768);    // 16*32*8
    float2* csh = (float2*)(smem + 131072 + 65536);    // 8*8

    const int tid = threadIdx.x;
    const int gb = blockIdx.x >> 5;        // batch group 0..3
    const int gu = blockIdx.x & 31;        // unit group 0..31
    const int u0 = gu * 16;
    const int b0 = gb * 8;

    // Preload Wh as col-pairs: wsh[d][cp], cp = gate*8 + up -> cols
    // gate*H + u0 + 2up, +1  (adjacent, so a natural float2 read).
    for (int idx = tid; idx < 512 * 32; idx += TPB_REC) {
        int d = idx >> 5, cp = idx & 31;
        int gate = cp >> 3, up = cp & 7;
        wsh[idx] = *(const float2*)(Wh + (size_t)d * G4H + gate * H_ + u0 + 2 * up);
    }
    if (tid < 64) csh[tid] = make_float2(0.f, 0.f);
    __syncthreads();

    const int cpq = tid & 7;
    const int bq  = (tid >> 3) & 1;
    const int ks  = tid >> 4;              // 0..15, 32 d each
    const int dbase = ks * 32;
    const float4* wf = ((const float4*)wsh) + (size_t)dbase * 16 + cpq * 2;
    const float4* hf = ((const float4*)hsh) + (size_t)dbase * 4 + bq * 2;

    const int up_g = tid >> 3;             // gate-phase unit-pair (tid < 64)
    const int b_g  = tid & 7;              // gate-phase batch

    unsigned* bar = &g_bar4[gb * 32];

    for (int t = 0; t < T_; t++) {
        const int rb = t & 1, wb = rb ^ 1;

        // prefetch xz (gate threads): 4 gates x 2 units for (b_g)
        float2 xz2[4];
        if (tid < 64) {
            const float* base = g_xz + ((size_t)t * B_ + b0 + b_g) * G4H + u0 + 2 * up_g;
            #pragma unroll
            for (int g = 0; g < 4; g++)
                xz2[g] = *(const float2*)(base + (size_t)g * H_);
        }

        float2 acc[4][4];
        #pragma unroll
        for (int j = 0; j < 4; j++)
            #pragma unroll
            for (int p = 0; p < 4; p++) acc[j][p] = make_float2(0.f, 0.f);

        if (t > 0) {
            // stage 16KB of h for this batch group (L2, duplicate on the fly)
            const float4* src = (const float4*)(g_hf[rb][gb]);
            #pragma unroll
            for (int i = 0; i < 4; i++) {
                int idx = tid + i * 256;          // 0..1023 float4 slots
                int d = idx >> 1, half = idx & 1;
                float4 v = __ldcg(src + idx);
                float4* dst = (float4*)hsh + (size_t)d * 4 + half * 2;
                dst[0] = make_float4(v.x, v.x, v.y, v.y);
                dst[1] = make_float4(v.z, v.z, v.w, v.w);
            }
            __syncthreads();

            #pragma unroll 2
            for (int d = 0; d < 32; d++) {
                float4 wA = wf[d * 16], wB = wf[d * 16 + 1];
                float4 hA = hf[d * 4],  hB = hf[d * 4 + 1];
                float2 w0 = make_float2(wA.x, wA.y), w1 = make_float2(wA.z, wA.w);
                float2 w2 = make_float2(wB.x, wB.y), w3 = make_float2(wB.z, wB.w);
                float2 h0 = make_float2(hA.x, hA.y), h1 = make_float2(hA.z, hA.w);
                float2 h2 = make_float2(hB.x, hB.y), h3 = make_float2(hB.z, hB.w);
                ffma2(acc[0][0], h0, w0); ffma2(acc[0][1], h1, w0);
                ffma2(acc[0][2], h2, w0); ffma2(acc[0][3], h3, w0);
                ffma2(acc[1][0], h0, w1); ffma2(acc[1][1], h1, w1);
                ffma2(acc[1][2], h2, w1); ffma2(acc[1][3], h3, w1);
                ffma2(acc[2][0], h0, w2); ffma2(acc[2][1], h1, w2);
                ffma2(acc[2][2], h2, w2); ffma2(acc[2][3], h3, w2);
                ffma2(acc[3][0], h0, w3); ffma2(acc[3][1], h1, w3);
                ffma2(acc[3][2], h2, w3); ffma2(acc[3][3], h3, w3);
            }
        }

        // write partials: zsh[ks][cp][b], thread covers cp=cpq*4..+3, b=bq*4..+3
        #pragma unroll
        for (int j = 0; j < 4; j++) {
            float2* zp = zsh + (size_t)ks * 256 + (cpq * 4 + j) * 8 + bq * 4;
            *(float4*)(zp + 0) = make_float4(acc[j][0].x, acc[j][0].y,
                                             acc[j][1].x, acc[j][1].y);
            *(float4*)(zp + 2) = make_float4(acc[j][2].x, acc[j][2].y,
                                             acc[j][3].x, acc[j][3].y);
        }
        __syncthreads();

        // gates: 64 threads = 8 unit-pairs x 8 batches; float2 = 2 units
        if (tid < 64) {
            float2 z[4];
            #pragma unroll
            for (int g = 0; g < 4; g++) {
                float2 s = xz2[g];
                int cp = g * 8 + up_g;
                #pragma unroll
                for (int k = 0; k < 16; k++) {
                    float2 v = zsh[k * 256 + cp * 8 + b_g];
                    s.x += v.x; s.y += v.y;
                }
                z[g] = s;
            }
            float2 ig = sig2(z[0]);
            float2 fg = sig2(z[1]);
            float2 gg = th2(z[2]);
            float2 og = sig2(z[3]);
            float2 cold = csh[up_g * 8 + b_g];
            float2 nc = make_float2(fg.x * cold.x + ig.x * gg.x,
                                    fg.y * cold.y + ig.y * gg.y);
            float2 tc = th2(nc);
            float2 nh = make_float2(og.x * tc.x, og.y * tc.y);
            csh[up_g * 8 + b_g] = nc;

            int u = u0 + 2 * up_g;
            float* hb = g_hf[wb][gb];
            hb[(u + 0) * 8 + b_g] = nh.x;
            hb[(u + 1) * 8 + b_g] = nh.y;
            *(float2*)(out + ((size_t)(b0 + b_g) * T_ + t) * H_ + u) = nh;
            __threadfence();
        }
        __syncthreads();

        // per-group barrier (32 CTAs, monotonic counter)
        if (tid == 0) {
            atomicAdd(bar, 1u);
            unsigned target = (unsigned)(t + 1) * 32u;
            while (*((volatile unsigned*)bar) < target) { }
        }
        __syncthreads();
    }

    // final states: this CTA owns (b0..b0+7) x (u0..u0+15)
    for (int idx = tid; idx < 128; idx += TPB_REC) {
        int b = b0 + (idx >> 4), u = u0 + (idx & 15);
        int len = read_length(lengths_raw, b);
        int lt = len > 0 ? len - 1 : 0;
        if (lt > T_ - 1) lt = T_ - 1;
        out[(size_t)B_ * T_ * H_ + (size_t)b * H_ + u] =
            out[((size_t)b * T_ + (size_t)lt) * H_ + u];
    }
    __syncthreads();

    // reset this group's counters for the next graph replay
    if (tid == 0) {
        unsigned ticket = atomicAdd(&g_exit4[gb * 32], 1u);
        if (ticket == 31u) {
            g_bar4[gb * 32] = 0;
            g_exit4[gb * 32] = 0;
            __threadfence();
        }
    }
}

// ---------------- launch ------------------------------------------------------
extern "C" void kernel_launch(void* const* d_in, const int* in_sizes, int n_in,
                              void* d_out, int out_size)
{
    const float* X       = (const float*)d_in[0];
    const int*   lengths = (const int*)d_in[1];   // int32/int64 autodetected
    const float* Wx      = (const float*)d_in[2];
    const float* Wh      = (const float*)d_in[3];
    const float* bias    = (const float*)d_in[4];
    float*       out     = (float*)d_out;

    dim3 g1(G4H / 128, (B_ * T_) / 128);
    gemm_xw_kernel<<<g1, 256>>>(X, Wx, bias);

    static const size_t SMEM_REC = 131072 + 32768 + 32768 + 512;  // 197,120 B
    cudaFuncSetAttribute(lstm_rec_kernel,
                         cudaFuncAttributeMaxDynamicSharedMemorySize, (int)SMEM_REC);
    lstm_rec_kernel<<<GRID_REC, TPB_REC, SMEM_REC>>>(Wh, lengths, out);
}